// round 6
// baseline (speedup 1.0000x reference)
#include <cuda_runtime.h>
#include <cstddef>

// Problem dims
#define LDIM 2
#define BDIM 16384
#define SDIM 512
#define N4   2048      // 4*S
#define KDIM 512       // S

// GEMM tiling
#define BM  128
#define BN  128
#define BKT 16
#define TM  8
#define TN  8

// Scratch for pre-activation z of one layer: [B, 4S] fp32 = 128 MB.
// __device__ global array is the sanctioned alloc-free scratch mechanism.
__device__ float g_z[(size_t)BDIM * N4];

union F2U { float2 f; unsigned long long u; };

// Packed dual-fp32 FMA (sm_100+). ptxas will not auto-fuse this from C++.
// NOTE: separate "=l" output + 3 inputs — the "+l" read-write form ICEs nvcc.
__device__ __forceinline__ float2 ffma2(float2 a, float2 b, float2 c) {
#if defined(__CUDA_ARCH__) && (__CUDA_ARCH__ >= 1000)
    F2U ua, ub, uc, ud;
    ua.f = a; ub.f = b; uc.f = c; ud.u = 0ull;
    asm("fma.rn.f32x2 %0, %1, %2, %3;"
        : "=l"(ud.u)
        : "l"(ua.u), "l"(ub.u), "l"(uc.u));
    return ud.f;
#else
    return make_float2(fmaf(a.x, b.x, c.x), fmaf(a.y, b.y, c.y));
#endif
}

// Z[B, 4S] = X[B,K] @ W[K,4S] + Hm[B,K] @ U[K,4S] + bias[4S]
// 256 threads, 128x128 block tile, 8x8 per-thread microtile, BK=16.
__global__ __launch_bounds__(256, 2)
void lstm_gemm_kernel(const float* __restrict__ X,
                      const float* __restrict__ Hm,
                      const float* __restrict__ W,
                      const float* __restrict__ U,
                      const float* __restrict__ bias)
{
    __shared__ float As[BKT][BM];   // A stored transposed: As[k][m]
    __shared__ float Bs[BKT][BN];

    const int tid = threadIdx.x;
    const int tx  = tid & 15;       // N direction (16 threads)
    const int ty  = tid >> 4;       // M direction (16 threads)
    const int m0  = blockIdx.y * BM;
    const int n0  = blockIdx.x * BN;

    float2 acc[TM][TN / 2];
#pragma unroll
    for (int i = 0; i < TM; ++i)
#pragma unroll
        for (int j = 0; j < TN / 2; ++j)
            acc[i][j] = make_float2(0.f, 0.f);

    // A-tile load mapping: 128 rows x 4 float4 = 512 vectors, 2 per thread.
    const int a_row0 = tid >> 2;    // 0..63 (i=1 adds 64)
    const int a_kv   = tid & 3;     // which float4 along K
    // B-tile load mapping: 16 rows x 32 float4 = 512 vectors, 2 per thread.
    const int b_k0   = tid >> 5;    // 0..7 (i=1 adds 8)
    const int b_nv   = tid & 31;

#pragma unroll 1
    for (int pair = 0; pair < 2; ++pair) {
        const float* Ap = pair ? Hm : X;
        const float* Bp = pair ? U  : W;

#pragma unroll 1
        for (int k0 = 0; k0 < KDIM; k0 += BKT) {
            // Load A tile (BM x BKT), store transposed into As
#pragma unroll
            for (int i = 0; i < 2; ++i) {
                const int row = a_row0 + i * 64;
                const float4 v = *reinterpret_cast<const float4*>(
                    Ap + (size_t)(m0 + row) * KDIM + k0 + a_kv * 4);
                As[a_kv * 4 + 0][row] = v.x;
                As[a_kv * 4 + 1][row] = v.y;
                As[a_kv * 4 + 2][row] = v.z;
                As[a_kv * 4 + 3][row] = v.w;
            }
            // Load B tile (BKT x BN)
#pragma unroll
            for (int i = 0; i < 2; ++i) {
                const int kr = b_k0 + i * 8;
                const float4 v = *reinterpret_cast<const float4*>(
                    Bp + (size_t)(k0 + kr) * N4 + n0 + b_nv * 4);
                *reinterpret_cast<float4*>(&Bs[kr][b_nv * 4]) = v;
            }
            __syncthreads();

#pragma unroll
            for (int kk = 0; kk < BKT; ++kk) {
                const float4 a0 = *reinterpret_cast<const float4*>(&As[kk][ty * TM]);
                const float4 a1 = *reinterpret_cast<const float4*>(&As[kk][ty * TM + 4]);
                const float4 b0 = *reinterpret_cast<const float4*>(&Bs[kk][tx * TN]);
                const float4 b1 = *reinterpret_cast<const float4*>(&Bs[kk][tx * TN + 4]);

                const float av[TM] = {a0.x, a0.y, a0.z, a0.w, a1.x, a1.y, a1.z, a1.w};
                const float2 bv[TN / 2] = {
                    make_float2(b0.x, b0.y), make_float2(b0.z, b0.w),
                    make_float2(b1.x, b1.y), make_float2(b1.z, b1.w)
                };
#pragma unroll
                for (int i = 0; i < TM; ++i) {
                    const float2 a2 = make_float2(av[i], av[i]);
#pragma unroll
                    for (int j = 0; j < TN / 2; ++j)
                        acc[i][j] = ffma2(a2, bv[j], acc[i][j]);
                }
            }
            __syncthreads();
        }
    }

    // Epilogue: + bias, store to scratch z
    const int nbase = n0 + tx * TN;
    const float4 bia0 = *reinterpret_cast<const float4*>(bias + nbase);
    const float4 bia1 = *reinterpret_cast<const float4*>(bias + nbase + 4);
#pragma unroll
    for (int i = 0; i < TM; ++i) {
        const int m = m0 + ty * TM + i;
        const float4 o0 = make_float4(acc[i][0].x + bia0.x, acc[i][0].y + bia0.y,
                                      acc[i][1].x + bia0.z, acc[i][1].y + bia0.w);
        const float4 o1 = make_float4(acc[i][2].x + bia1.x, acc[i][2].y + bia1.y,
                                      acc[i][3].x + bia1.z, acc[i][3].y + bia1.w);
        float* zr = g_z + (size_t)m * N4 + nbase;
        *reinterpret_cast<float4*>(zr)     = o0;
        *reinterpret_cast<float4*>(zr + 4) = o1;
    }
}

__device__ __forceinline__ float sigf(float x) {
    return 1.f / (1.f + expf(-x));
}

// Gate epilogue: reads z (scratch) + c_tm1, writes h and c.
// One thread handles 4 consecutive s positions (float4).
__global__ __launch_bounds__(256)
void lstm_gates_kernel(const float* __restrict__ c_tm1,
                       float* __restrict__ h_out,
                       float* __restrict__ c_out)
{
    const int idx = blockIdx.x * blockDim.x + threadIdx.x;  // over B*S/4
    const int b  = idx / (SDIM / 4);
    const int s4 = idx - b * (SDIM / 4);

    const float* zr = g_z + (size_t)b * N4 + s4 * 4;
    const float4 zi = *reinterpret_cast<const float4*>(zr);
    const float4 zf = *reinterpret_cast<const float4*>(zr + SDIM);
    const float4 zg = *reinterpret_cast<const float4*>(zr + 2 * SDIM);
    const float4 zo = *reinterpret_cast<const float4*>(zr + 3 * SDIM);
    const float4 cp = *reinterpret_cast<const float4*>(c_tm1 + (size_t)idx * 4);

    float4 c, h;
    c.x = sigf(zf.x) * cp.x + sigf(zi.x) * tanhf(zg.x);
    c.y = sigf(zf.y) * cp.y + sigf(zi.y) * tanhf(zg.y);
    c.z = sigf(zf.z) * cp.z + sigf(zi.z) * tanhf(zg.z);
    c.w = sigf(zf.w) * cp.w + sigf(zi.w) * tanhf(zg.w);
    h.x = sigf(zo.x) * tanhf(c.x);
    h.y = sigf(zo.y) * tanhf(c.y);
    h.z = sigf(zo.z) * tanhf(c.z);
    h.w = sigf(zo.w) * tanhf(c.w);

    *reinterpret_cast<float4*>(h_out + (size_t)idx * 4) = h;
    *reinterpret_cast<float4*>(c_out + (size_t)idx * 4) = c;
}

extern "C" void kernel_launch(void* const* d_in, const int* in_sizes, int n_in,
                              void* d_out, int out_size)
{
    const float* inputs  = (const float*)d_in[0];  // [B, S]
    const float* prev_c  = (const float*)d_in[1];  // [L, B, S] -> used as h_tm1 (NNI swap)
    const float* prev_h  = (const float*)d_in[2];  // [L, B, S] -> used as c_tm1 (NNI swap)
    const float* kernels = (const float*)d_in[3];  // [L, S, 4S]
    const float* rec_k   = (const float*)d_in[4];  // [L, S, 4S]
    const float* biases  = (const float*)d_in[5];  // [L, 4S]
    float* out = (float*)d_out;                    // [L, 2, B, S]

    const size_t BS = (size_t)BDIM * SDIM;          // 8,388,608
    const size_t WSTRIDE = (size_t)SDIM * N4;       // per-layer weight stride

    const dim3 gemm_grid(N4 / BN, BDIM / BM);       // (16, 128)
    const int gates_blocks = (int)(BS / (256 * 4)); // 8192

    // ---- Layer 0 ----
    // z = inputs @ W0 + prev_c[0] @ U0 + b0
    lstm_gemm_kernel<<<gemm_grid, 256>>>(inputs, prev_c,
                                         kernels, rec_k, biases);
    // h0 -> out[0,0], c0 -> out[0,1]; c_tm1 = prev_h[0]
    lstm_gates_kernel<<<gates_blocks, 256>>>(prev_h, out, out + BS);

    // ---- Layer 1 ----  (input x = c0 = out[0,1])
    lstm_gemm_kernel<<<gemm_grid, 256>>>(out + BS, prev_c + BS,
                                         kernels + WSTRIDE, rec_k + WSTRIDE,
                                         biases + N4);
    lstm_gates_kernel<<<gates_blocks, 256>>>(prev_h + BS,
                                             out + 2 * BS, out + 3 * BS);
}

// round 12
// speedup vs baseline: 3.3286x; 3.3286x over previous
#include <cuda_runtime.h>
#include <cstdint>
#include <cstddef>

// ---------------- Problem dims ----------------
#define LDIM 2
#define BDIM 16384
#define SDIM 512
#define N4   2048

// ---------------- GEMM tiling ----------------
#define TILE_M 128
#define TILE_N 128
#define BK     32
#define NCHUNK 32          // 2 operand pairs * (512/32)

// SMEM (floats): A buffers pitch 36 (conflict-free frag reads), B pitch 136.
#define APITCH 36
#define BPITCH 136
#define A_FLOATS (TILE_M * APITCH)     // 4608
#define B_FLOATS (BK * BPITCH)         // 4352
#define SMEM_TOTAL ((2 * A_FLOATS + 2 * B_FLOATS) * 4)   // 71680 bytes

// ---------------- scratch (__device__ globals; alloc-free) ----------------
__device__ float g_z  [(size_t)BDIM * N4];              // preactivations (one layer)
__device__ float g_wt [(size_t)LDIM * 2 * SDIM * N4];   // tf32-rounded weights: [W(l0,l1) | U(l0,l1)]
__device__ float g_xr [(size_t)BDIM * SDIM];            // rounded inputs
__device__ float g_hr [(size_t)LDIM * BDIM * SDIM];     // rounded prev_c (= h_tm1, NNI swap)
__device__ float g_c0r[(size_t)BDIM * SDIM];            // rounded c0 (layer-1 input)

// ---------------- helpers ----------------
__device__ __forceinline__ uint32_t smem_u32(const void* p) {
    uint32_t a;
    asm("{ .reg .u64 t; cvta.to.shared.u64 t, %1; cvt.u32.u64 %0, t; }" : "=r"(a) : "l"(p));
    return a;
}
__device__ __forceinline__ float tf32r(float x) {
    float r;
    asm("cvt.rna.tf32.f32 %0, %1;" : "=f"(r) : "f"(x));
    return r;
}
__device__ __forceinline__ void cp16(uint32_t s, const void* g) {
    asm volatile("cp.async.cg.shared.global [%0], [%1], 16;" :: "r"(s), "l"(g) : "memory");
}
__device__ __forceinline__ void cp_commit() {
    asm volatile("cp.async.commit_group;" ::: "memory");
}
__device__ __forceinline__ void cp_wait_all() {
    asm volatile("cp.async.wait_group 0;" ::: "memory");
}
// m16n8k8 tf32 warp MMA (sm_80 baseline -> HMMA on sm_103, no "a" target needed)
__device__ __forceinline__ void mma8(float* d, const uint32_t* a, const uint32_t* b) {
    asm volatile(
        "mma.sync.aligned.m16n8k8.row.col.f32.tf32.tf32.f32 "
        "{%0,%1,%2,%3}, {%4,%5,%6,%7}, {%8,%9}, {%10,%11,%12,%13};"
        : "=f"(d[0]), "=f"(d[1]), "=f"(d[2]), "=f"(d[3])
        : "r"(a[0]), "r"(a[1]), "r"(a[2]), "r"(a[3]),
          "r"(b[0]), "r"(b[1]),
          "f"(d[0]), "f"(d[1]), "f"(d[2]), "f"(d[3]));
}

// ---------------- elementwise tf32 round ----------------
__global__ void round_tf32_kernel(const float* __restrict__ src, float* __restrict__ dst)
{
    const size_t i = (size_t)blockIdx.x * blockDim.x + threadIdx.x;
    const float4 v = reinterpret_cast<const float4*>(src)[i];
    float4 o;
    o.x = tf32r(v.x); o.y = tf32r(v.y); o.z = tf32r(v.z); o.w = tf32r(v.w);
    reinterpret_cast<float4*>(dst)[i] = o;
}

// ---------------- tile staging ----------------
__device__ __forceinline__ void stage(uint32_t sbase, int buf,
                                      const float* __restrict__ Ab,
                                      const float* __restrict__ Bb,
                                      int m0, int n0, int k0, int tid)
{
    const uint32_t sa = sbase + (buf ? (uint32_t)A_FLOATS * 4u : 0u);
    const uint32_t sb = sbase + (uint32_t)(2 * A_FLOATS) * 4u
                              + (buf ? (uint32_t)B_FLOATS * 4u : 0u);
    // A tile: 128 rows x 32 k  -> 1024 float4, 8 per thread
#pragma unroll
    for (int i = 0; i < 8; ++i) {
        const int v = tid + i * 128;
        const int m = v >> 3, kv = v & 7;
        cp16(sa + (uint32_t)(m * APITCH + kv * 4) * 4u,
             Ab + (size_t)(m0 + m) * SDIM + k0 + kv * 4);
    }
    // B tile: 32 k-rows x 128 n -> 1024 float4, 8 per thread (weights native [k][n])
#pragma unroll
    for (int i = 0; i < 8; ++i) {
        const int v = tid + i * 128;
        const int k = v >> 5, nv = v & 31;
        cp16(sb + (uint32_t)(k * BPITCH + nv * 4) * 4u,
             Bb + (size_t)(k0 + k) * N4 + n0 + nv * 4);
    }
}

// ---------------- per-chunk compute ----------------
__device__ __forceinline__ void compute_chunk(const float* __restrict__ As,
                                              const float* __restrict__ Bs,
                                              float (&acc)[4][8][4],
                                              int lane, int wm, int wn)
{
#pragma unroll
    for (int ks = 0; ks < 4; ++ks) {
        const int ka = ks * 8 + (lane & 3);
        const int ra = wm + (lane >> 2);
        uint32_t a[4][4];
#pragma unroll
        for (int mt = 0; mt < 4; ++mt) {
            const float* ap = As + (size_t)(ra + mt * 16) * APITCH + ka;
            a[mt][0] = __float_as_uint(ap[0]);
            a[mt][1] = __float_as_uint(ap[8 * APITCH]);
            a[mt][2] = __float_as_uint(ap[4]);
            a[mt][3] = __float_as_uint(ap[8 * APITCH + 4]);
        }
        uint32_t b[8][2];
        const int kb = ks * 8 + (lane & 3);
        const int nb = wn + (lane >> 2);
#pragma unroll
        for (int nt = 0; nt < 8; ++nt) {
            const float* bp = Bs + (size_t)kb * BPITCH + nb + nt * 8;
            b[nt][0] = __float_as_uint(bp[0]);
            b[nt][1] = __float_as_uint(bp[4 * BPITCH]);
        }
#pragma unroll
        for (int mt = 0; mt < 4; ++mt)
#pragma unroll
            for (int nt = 0; nt < 8; ++nt)
                mma8(acc[mt][nt], a[mt], b[nt]);
    }
}

// ---------------- fused dual-GEMM: z = X@W + H@U + bias ----------------
__global__ __launch_bounds__(128, 2)
void lstm_gemm_tc(const float* __restrict__ A1, const float* __restrict__ A2,
                  const float* __restrict__ Bw, const float* __restrict__ Bu,
                  const float* __restrict__ bias)
{
    extern __shared__ float sm[];
    const uint32_t sbase = smem_u32(sm);
    const int tid  = threadIdx.x;
    const int lane = tid & 31;
    const int warp = tid >> 5;
    const int wm = (warp >> 1) * 64;
    const int wn = (warp & 1) * 64;
    const int m0 = blockIdx.y * TILE_M;
    const int n0 = blockIdx.x * TILE_N;

    float acc[4][8][4];
#pragma unroll
    for (int mt = 0; mt < 4; ++mt)
#pragma unroll
        for (int nt = 0; nt < 8; ++nt)
#pragma unroll
            for (int r = 0; r < 4; ++r)
                acc[mt][nt][r] = 0.f;

    // prologue
    stage(sbase, 0, A1, Bw, m0, n0, 0, tid);
    cp_commit();

#pragma unroll 1
    for (int c = 0; c < NCHUNK; ++c) {
        cp_wait_all();
        __syncthreads();
        if (c + 1 < NCHUNK) {
            const int cn = c + 1;
            stage(sbase, cn & 1,
                  (cn < 16) ? A1 : A2, (cn < 16) ? Bw : Bu,
                  m0, n0, (cn & 15) * BK, tid);
            cp_commit();
        }
        const float* As = sm + ((c & 1) ? A_FLOATS : 0);
        const float* Bs = sm + 2 * A_FLOATS + ((c & 1) ? B_FLOATS : 0);
        compute_chunk(As, Bs, acc, lane, wm, wn);
    }

    // epilogue: + bias, store z
    const int r0 = lane >> 2;
    const int cc = (lane & 3) * 2;
#pragma unroll
    for (int mt = 0; mt < 4; ++mt) {
#pragma unroll
        for (int nt = 0; nt < 8; ++nt) {
            const int m = m0 + wm + mt * 16 + r0;
            const int n = n0 + wn + nt * 8 + cc;
            const float2 bv = *reinterpret_cast<const float2*>(bias + n);
            float2 v0 = make_float2(acc[mt][nt][0] + bv.x, acc[mt][nt][1] + bv.y);
            float2 v1 = make_float2(acc[mt][nt][2] + bv.x, acc[mt][nt][3] + bv.y);
            *reinterpret_cast<float2*>(g_z + (size_t)m * N4 + n) = v0;
            *reinterpret_cast<float2*>(g_z + (size_t)(m + 8) * N4 + n) = v1;
        }
    }
}

// ---------------- gates ----------------
__device__ __forceinline__ float sigf(float x) { return 1.f / (1.f + expf(-x)); }

__global__ __launch_bounds__(256)
void lstm_gates_kernel(const float* __restrict__ c_tm1,
                       float* __restrict__ h_out,
                       float* __restrict__ c_out,
                       float* __restrict__ c_round_out)   // may be null
{
    const int idx = blockIdx.x * blockDim.x + threadIdx.x;   // over B*S/4
    const int b  = idx / (SDIM / 4);
    const int s4 = idx - b * (SDIM / 4);

    const float* zr = g_z + (size_t)b * N4 + s4 * 4;
    const float4 zi = *reinterpret_cast<const float4*>(zr);
    const float4 zf = *reinterpret_cast<const float4*>(zr + SDIM);
    const float4 zg = *reinterpret_cast<const float4*>(zr + 2 * SDIM);
    const float4 zo = *reinterpret_cast<const float4*>(zr + 3 * SDIM);
    const float4 cp = *reinterpret_cast<const float4*>(c_tm1 + (size_t)idx * 4);

    float4 c, h;
    c.x = sigf(zf.x) * cp.x + sigf(zi.x) * tanhf(zg.x);
    c.y = sigf(zf.y) * cp.y + sigf(zi.y) * tanhf(zg.y);
    c.z = sigf(zf.z) * cp.z + sigf(zi.z) * tanhf(zg.z);
    c.w = sigf(zf.w) * cp.w + sigf(zi.w) * tanhf(zg.w);
    h.x = sigf(zo.x) * tanhf(c.x);
    h.y = sigf(zo.y) * tanhf(c.y);
    h.z = sigf(zo.z) * tanhf(c.z);
    h.w = sigf(zo.w) * tanhf(c.w);

    *reinterpret_cast<float4*>(h_out + (size_t)idx * 4) = h;
    *reinterpret_cast<float4*>(c_out + (size_t)idx * 4) = c;
    if (c_round_out) {
        float4 cr;
        cr.x = tf32r(c.x); cr.y = tf32r(c.y); cr.z = tf32r(c.z); cr.w = tf32r(c.w);
        *reinterpret_cast<float4*>(c_round_out + (size_t)idx * 4) = cr;
    }
}

// ---------------- launch ----------------
extern "C" void kernel_launch(void* const* d_in, const int* in_sizes, int n_in,
                              void* d_out, int out_size)
{
    const float* inputs  = (const float*)d_in[0];  // [B, S]
    const float* prev_c  = (const float*)d_in[1];  // [L, B, S] -> h_tm1 (NNI swap)
    const float* prev_h  = (const float*)d_in[2];  // [L, B, S] -> c_tm1 (NNI swap)
    const float* kernels = (const float*)d_in[3];  // [L, S, 4S]
    const float* rec_k   = (const float*)d_in[4];  // [L, S, 4S]
    const float* biases  = (const float*)d_in[5];  // [L, 4S]
    float* out = (float*)d_out;                    // [L, 2, B, S]

    const size_t BS      = (size_t)BDIM * SDIM;         // 8,388,608
    const size_t WHALF   = (size_t)LDIM * SDIM * N4;    // 2,097,152 (all layers, one op)
    const size_t WLAYER  = (size_t)SDIM * N4;           // 1,048,576

    float *p_xr, *p_hr, *p_c0r, *p_wt;
    cudaGetSymbolAddress((void**)&p_xr,  g_xr);
    cudaGetSymbolAddress((void**)&p_hr,  g_hr);
    cudaGetSymbolAddress((void**)&p_c0r, g_c0r);
    cudaGetSymbolAddress((void**)&p_wt,  g_wt);

    cudaFuncSetAttribute(lstm_gemm_tc,
                         cudaFuncAttributeMaxDynamicSharedMemorySize, SMEM_TOTAL);

    // precompute: tf32-round weights (native [k][n] layout) and activations
    round_tf32_kernel<<<(unsigned)(BS / 1024), 256>>>(inputs, p_xr);
    round_tf32_kernel<<<(unsigned)(2 * BS / 1024), 256>>>(prev_c, p_hr);
    round_tf32_kernel<<<(unsigned)(WHALF / 1024), 256>>>(kernels, p_wt);
    round_tf32_kernel<<<(unsigned)(WHALF / 1024), 256>>>(rec_k, p_wt + WHALF);

    const dim3 gemm_grid(N4 / TILE_N, BDIM / TILE_M);   // (16, 128)
    const int gates_blocks = (int)(BS / (256 * 4));      // 8192

    // ---- Layer 0 ----
    lstm_gemm_tc<<<gemm_grid, 128, SMEM_TOTAL>>>(p_xr, p_hr,
                                                 p_wt, p_wt + WHALF, biases);
    lstm_gates_kernel<<<gates_blocks, 256>>>(prev_h, out, out + BS, p_c0r);

    // ---- Layer 1 ---- (input x = c0, rounded copy in g_c0r)
    lstm_gemm_tc<<<gemm_grid, 128, SMEM_TOTAL>>>(p_c0r, p_hr + BS,
                                                 p_wt + WLAYER, p_wt + WHALF + WLAYER,
                                                 biases + N4);
    lstm_gates_kernel<<<gates_blocks, 256>>>(prev_h + BS, out + 2 * BS, out + 3 * BS,
                                             nullptr);
}

// round 14
// speedup vs baseline: 3.5452x; 1.0651x over previous
#include <cuda_runtime.h>
#include <cstdint>
#include <cstddef>

// ---------------- Problem dims ----------------
#define LDIM 2
#define BDIM 16384
#define SDIM 512
#define N4   2048

// ---------------- GEMM tiling ----------------
#define TILE_M 128
#define TILE_N 128
#define BK     32
#define NCHUNK 32          // 2 operand pairs * (512/32)
#define NSTAGE 3

// SMEM (floats): A pitch 36 (bank = lane, conflict-free), B pitch 136.
#define APITCH 36
#define BPITCH 136
#define A_FLOATS (TILE_M * APITCH)     // 4608
#define B_FLOATS (BK * BPITCH)         // 4352
#define STAGE_FLOATS (A_FLOATS + B_FLOATS)            // 8960
#define SMEM_TOTAL (NSTAGE * STAGE_FLOATS * 4)        // 107520 bytes

// ---------------- scratch (__device__ global; alloc-free) ----------------
__device__ float g_z[(size_t)BDIM * N4];              // preactivations (one layer)

// ---------------- helpers ----------------
__device__ __forceinline__ uint32_t smem_u32(const void* p) {
    uint32_t a;
    asm("{ .reg .u64 t; cvta.to.shared.u64 t, %1; cvt.u32.u64 %0, t; }" : "=r"(a) : "l"(p));
    return a;
}
__device__ __forceinline__ void cp16(uint32_t s, const void* g) {
    asm volatile("cp.async.cg.shared.global [%0], [%1], 16;" :: "r"(s), "l"(g) : "memory");
}
__device__ __forceinline__ void cp_commit() {
    asm volatile("cp.async.commit_group;" ::: "memory");
}
__device__ __forceinline__ void cp_wait1() {
    asm volatile("cp.async.wait_group 1;" ::: "memory");
}
__device__ __forceinline__ void cp_wait0() {
    asm volatile("cp.async.wait_group 0;" ::: "memory");
}
// m16n8k8 tf32 warp MMA (sm_80 baseline; fp32 inputs truncated to tf32 by HW)
__device__ __forceinline__ void mma8(float* d, const uint32_t* a, const uint32_t* b) {
    asm volatile(
        "mma.sync.aligned.m16n8k8.row.col.f32.tf32.tf32.f32 "
        "{%0,%1,%2,%3}, {%4,%5,%6,%7}, {%8,%9}, {%10,%11,%12,%13};"
        : "=f"(d[0]), "=f"(d[1]), "=f"(d[2]), "=f"(d[3])
        : "r"(a[0]), "r"(a[1]), "r"(a[2]), "r"(a[3]),
          "r"(b[0]), "r"(b[1]),
          "f"(d[0]), "f"(d[1]), "f"(d[2]), "f"(d[3]));
}

// ---------------- tile staging ----------------
__device__ __forceinline__ void stage(uint32_t sbase, int slot,
                                      const float* __restrict__ Ab,
                                      const float* __restrict__ Bb,
                                      int m0, int n0, int k0, int tid)
{
    const uint32_t sa = sbase + (uint32_t)(slot * STAGE_FLOATS) * 4u;
    const uint32_t sb = sa + (uint32_t)A_FLOATS * 4u;
    // A tile: 128 rows x 32 k  -> 1024 float4, 8 per thread
#pragma unroll
    for (int i = 0; i < 8; ++i) {
        const int v = tid + i * 128;
        const int m = v >> 3, kv = v & 7;
        cp16(sa + (uint32_t)(m * APITCH + kv * 4) * 4u,
             Ab + (size_t)(m0 + m) * SDIM + k0 + kv * 4);
    }
    // B tile: 32 k-rows x 128 n -> 1024 float4, 8 per thread (weights native [k][n])
#pragma unroll
    for (int i = 0; i < 8; ++i) {
        const int v = tid + i * 128;
        const int k = v >> 5, nv = v & 31;
        cp16(sb + (uint32_t)(k * BPITCH + nv * 4) * 4u,
             Bb + (size_t)(k0 + k) * N4 + n0 + nv * 4);
    }
}

// ---------------- per-chunk compute ----------------
__device__ __forceinline__ void compute_chunk(const float* __restrict__ As,
                                              const float* __restrict__ Bs,
                                              float (&acc)[4][8][4],
                                              int lane, int wm, int wn)
{
#pragma unroll
    for (int ks = 0; ks < 4; ++ks) {
        const int ka = ks * 8 + (lane & 3);
        const int ra = wm + (lane >> 2);
        uint32_t a[4][4];
#pragma unroll
        for (int mt = 0; mt < 4; ++mt) {
            const float* ap = As + (size_t)(ra + mt * 16) * APITCH + ka;
            a[mt][0] = __float_as_uint(ap[0]);
            a[mt][1] = __float_as_uint(ap[8 * APITCH]);
            a[mt][2] = __float_as_uint(ap[4]);
            a[mt][3] = __float_as_uint(ap[8 * APITCH + 4]);
        }
        uint32_t b[8][2];
        const int kb = ks * 8 + (lane & 3);
        const int nb = wn + (lane >> 2);
#pragma unroll
        for (int nt = 0; nt < 8; ++nt) {
            const float* bp = Bs + (size_t)kb * BPITCH + nb + nt * 8;
            b[nt][0] = __float_as_uint(bp[0]);
            b[nt][1] = __float_as_uint(bp[4 * BPITCH]);
        }
#pragma unroll
        for (int mt = 0; mt < 4; ++mt)
#pragma unroll
            for (int nt = 0; nt < 8; ++nt)
                mma8(acc[mt][nt], a[mt], b[nt]);
    }
}

// ---------------- fused dual-GEMM: z = X@W + H@U + bias ----------------
__global__ __launch_bounds__(128, 2)
void lstm_gemm_tc(const float* __restrict__ A1, const float* __restrict__ A2,
                  const float* __restrict__ Bw, const float* __restrict__ Bu,
                  const float* __restrict__ bias)
{
    extern __shared__ float sm[];
    const uint32_t sbase = smem_u32(sm);
    const int tid  = threadIdx.x;
    const int lane = tid & 31;
    const int warp = tid >> 5;
    const int wm = (warp >> 1) * 64;
    const int wn = (warp & 1) * 64;
    const int m0 = blockIdx.y * TILE_M;
    const int n0 = blockIdx.x * TILE_N;

    float acc[4][8][4];
#pragma unroll
    for (int mt = 0; mt < 4; ++mt)
#pragma unroll
        for (int nt = 0; nt < 8; ++nt)
#pragma unroll
            for (int r = 0; r < 4; ++r)
                acc[mt][nt][r] = 0.f;

    // prologue: stage chunks 0 and 1
    stage(sbase, 0, A1, Bw, m0, n0, 0, tid);
    cp_commit();
    stage(sbase, 1, A1, Bw, m0, n0, BK, tid);
    cp_commit();

#pragma unroll 1
    for (int c = 0; c < NCHUNK; ++c) {
        if (c >= NCHUNK - 2) cp_wait0(); else cp_wait1();   // chunk c resident
        __syncthreads();                                     // all readers of slot (c+2)%3 done
        if (c + 2 < NCHUNK) {
            const int cn = c + 2;
            stage(sbase, cn % NSTAGE,
                  (cn < 16) ? A1 : A2, (cn < 16) ? Bw : Bu,
                  m0, n0, (cn & 15) * BK, tid);
            cp_commit();
        }
        const float* st = sm + (c % NSTAGE) * STAGE_FLOATS;
        compute_chunk(st, st + A_FLOATS, acc, lane, wm, wn);
    }

    // epilogue: + bias, store z
    const int r0 = lane >> 2;
    const int cc = (lane & 3) * 2;
#pragma unroll
    for (int mt = 0; mt < 4; ++mt) {
#pragma unroll
        for (int nt = 0; nt < 8; ++nt) {
            const int m = m0 + wm + mt * 16 + r0;
            const int n = n0 + wn + nt * 8 + cc;
            const float2 bv = *reinterpret_cast<const float2*>(bias + n);
            float2 v0 = make_float2(acc[mt][nt][0] + bv.x, acc[mt][nt][1] + bv.y);
            float2 v1 = make_float2(acc[mt][nt][2] + bv.x, acc[mt][nt][3] + bv.y);
            *reinterpret_cast<float2*>(g_z + (size_t)m * N4 + n) = v0;
            *reinterpret_cast<float2*>(g_z + (size_t)(m + 8) * N4 + n) = v1;
        }
    }
}

// ---------------- gates ----------------
__device__ __forceinline__ float sigf(float x) { return 1.f / (1.f + expf(-x)); }

__global__ __launch_bounds__(256)
void lstm_gates_kernel(const float* __restrict__ c_tm1,
                       float* __restrict__ h_out,
                       float* __restrict__ c_out)
{
    const int idx = blockIdx.x * blockDim.x + threadIdx.x;   // over B*S/4
    const int b  = idx / (SDIM / 4);
    const int s4 = idx - b * (SDIM / 4);

    const float* zr = g_z + (size_t)b * N4 + s4 * 4;
    const float4 zi = *reinterpret_cast<const float4*>(zr);
    const float4 zf = *reinterpret_cast<const float4*>(zr + SDIM);
    const float4 zg = *reinterpret_cast<const float4*>(zr + 2 * SDIM);
    const float4 zo = *reinterpret_cast<const float4*>(zr + 3 * SDIM);
    const float4 cp = *reinterpret_cast<const float4*>(c_tm1 + (size_t)idx * 4);

    float4 c, h;
    c.x = sigf(zf.x) * cp.x + sigf(zi.x) * tanhf(zg.x);
    c.y = sigf(zf.y) * cp.y + sigf(zi.y) * tanhf(zg.y);
    c.z = sigf(zf.z) * cp.z + sigf(zi.z) * tanhf(zg.z);
    c.w = sigf(zf.w) * cp.w + sigf(zi.w) * tanhf(zg.w);
    h.x = sigf(zo.x) * tanhf(c.x);
    h.y = sigf(zo.y) * tanhf(c.y);
    h.z = sigf(zo.z) * tanhf(c.z);
    h.w = sigf(zo.w) * tanhf(c.w);

    *reinterpret_cast<float4*>(h_out + (size_t)idx * 4) = h;
    *reinterpret_cast<float4*>(c_out + (size_t)idx * 4) = c;
}

// ---------------- launch ----------------
extern "C" void kernel_launch(void* const* d_in, const int* in_sizes, int n_in,
                              void* d_out, int out_size)
{
    const float* inputs  = (const float*)d_in[0];  // [B, S]
    const float* prev_c  = (const float*)d_in[1];  // [L, B, S] -> h_tm1 (NNI swap)
    const float* prev_h  = (const float*)d_in[2];  // [L, B, S] -> c_tm1 (NNI swap)
    const float* kernels = (const float*)d_in[3];  // [L, S, 4S]
    const float* rec_k   = (const float*)d_in[4];  // [L, S, 4S]
    const float* biases  = (const float*)d_in[5];  // [L, 4S]
    float* out = (float*)d_out;                    // [L, 2, B, S]

    const size_t BS     = (size_t)BDIM * SDIM;      // 8,388,608
    const size_t WLAYER = (size_t)SDIM * N4;        // 1,048,576

    cudaFuncSetAttribute(lstm_gemm_tc,
                         cudaFuncAttributeMaxDynamicSharedMemorySize, SMEM_TOTAL);

    const dim3 gemm_grid(N4 / TILE_N, BDIM / TILE_M);   // (16, 128)
    const int gates_blocks = (int)(BS / (256 * 4));      // 8192

    // ---- Layer 0 ----  z = inputs@W0 + prev_c[0]@U0 + b0  (tf32 truncation in HW)
    lstm_gemm_tc<<<gemm_grid, 128, SMEM_TOTAL>>>(inputs, prev_c,
                                                 kernels, rec_k, biases);
    lstm_gates_kernel<<<gates_blocks, 256>>>(prev_h, out, out + BS);

    // ---- Layer 1 ----  input x = c0 = out[0,1]
    lstm_gemm_tc<<<gemm_grid, 128, SMEM_TOTAL>>>(out + BS, prev_c + BS,
                                                 kernels + WLAYER, rec_k + WLAYER,
                                                 biases + N4);
    lstm_gates_kernel<<<gates_blocks, 256>>>(prev_h + BS, out + 2 * BS, out + 3 * BS);
}